// round 3
// baseline (speedup 1.0000x reference)
#include <cuda_runtime.h>
#include <stdint.h>
#include <math.h>

// HermanModel spiking network — bit-faithful replication of the JAX/XLA-CPU
// reference (partitionable Threefry scheme, XLA ErfInv expansion, sequential
// edge-order scatter accumulation).

#define NN      100000
#define HALF    50000
#define EE      6400000
#define MAXDEG  192
#define NSTEPS  100

struct __align__(8) Edge { int src; float w; };

// Static scratch (allocation rules forbid cudaMalloc).
__device__ int      g_is64;
__device__ int      g_cnt[NN];
__device__ int      g_deg[NN];
__device__ unsigned g_key[(size_t)MAXDEG * NN];   // packed (eid<<8)|slot
__device__ Edge     g_tmp[(size_t)MAXDEG * NN];   // binned (unordered)
__device__ Edge     g_ell[(size_t)MAXDEG * NN];   // edge-id-ordered ELL
__device__ float    g_actA[NN];
__device__ float    g_actB[NN];

// ---------------- Threefry-2x32 (JAX's 20-round cipher) ----------------
__host__ __device__ __forceinline__ unsigned rotl32(unsigned x, int r) {
    return (x << r) | (x >> (32 - r));
}

__host__ __device__ __forceinline__ void tf2x32(unsigned k0, unsigned k1,
                                                unsigned x0, unsigned x1,
                                                unsigned &o0, unsigned &o1)
{
    unsigned k2 = k0 ^ k1 ^ 0x1BD11BDAu;
    x0 += k0; x1 += k1;
#define TF_R(r) { x0 += x1; x1 = rotl32(x1, r); x1 ^= x0; }
#define TF_G1   TF_R(13) TF_R(15) TF_R(26) TF_R(6)
#define TF_G2   TF_R(17) TF_R(29) TF_R(16) TF_R(24)
    TF_G1  x0 += k1; x1 += k2 + 1u;
    TF_G2  x0 += k2; x1 += k0 + 2u;
    TF_G1  x0 += k0; x1 += k1 + 3u;
    TF_G2  x0 += k1; x1 += k2 + 4u;
    TF_G1  x0 += k2; x1 += k0 + 5u;
#undef TF_G1
#undef TF_G2
#undef TF_R
    o0 = x0; o1 = x1;
}

// ---------------- XLA math replication (strict f32, no FMA) ----------------
// XLA EmitLog1p: |x| < 1e-4 -> ((-0.5*x)+1)*x ; else log(1+x).
__device__ __forceinline__ float xla_log1p(float v) {
    if (fabsf(v) < 1e-4f)
        return __fmul_rn(__fadd_rn(__fmul_rn(-0.5f, v), 1.0f), v);
    return (float)log((double)__fadd_rn(v, 1.0f));   // correctly-rounded logf
}

// XLA ErfInv f32 expansion (Giles polynomial), Horner as add(c, mul(p,w)).
__device__ __forceinline__ float xla_erfinv(float x) {
    float w = -xla_log1p(-__fmul_rn(x, x));
    float p;
    if (w < 5.0f) {
        w = __fadd_rn(w, -2.5f);
        p =  2.81022636e-08f;
        p = __fadd_rn( 3.43273939e-07f, __fmul_rn(p, w));
        p = __fadd_rn(-3.5233877e-06f,  __fmul_rn(p, w));
        p = __fadd_rn(-4.39150654e-06f, __fmul_rn(p, w));
        p = __fadd_rn( 0.00021858087f,  __fmul_rn(p, w));
        p = __fadd_rn(-0.00125372503f,  __fmul_rn(p, w));
        p = __fadd_rn(-0.00417768164f,  __fmul_rn(p, w));
        p = __fadd_rn( 0.246640727f,    __fmul_rn(p, w));
        p = __fadd_rn( 1.50140941f,     __fmul_rn(p, w));
    } else {
        w = __fadd_rn(sqrtf(w), -3.0f);
        p = -0.000200214257f;
        p = __fadd_rn( 0.000100950558f, __fmul_rn(p, w));
        p = __fadd_rn( 0.00134934322f,  __fmul_rn(p, w));
        p = __fadd_rn(-0.00367342844f,  __fmul_rn(p, w));
        p = __fadd_rn( 0.00573950773f,  __fmul_rn(p, w));
        p = __fadd_rn(-0.0076224613f,   __fmul_rn(p, w));
        p = __fadd_rn( 0.00943887047f,  __fmul_rn(p, w));
        p = __fadd_rn( 1.00167406f,     __fmul_rn(p, w));
        p = __fadd_rn( 2.83297682f,     __fmul_rn(p, w));
    }
    return __fmul_rn(p, x);
}

// jax.random.normal: u = max(lo, f*2.0f + lo), lo = nextafter(-1,0);
// (hi-lo) rounds (tie-to-even) to exactly 2.0f. normal = f32(sqrt2)*erfinv(u).
__device__ __forceinline__ float bits_to_normal(unsigned bits) {
    const float LO = -0.99999994f;   // 0xBF7FFFFF
    float f = __fadd_rn(__uint_as_float((bits >> 9) | 0x3F800000u), -1.0f);
    float u = __fadd_rn(__fmul_rn(f, 2.0f), LO);
    u = fmaxf(LO, u);
    return __fmul_rn(1.41421356f, xla_erfinv(u));    // 0x3FB504F3
}

// ---------------- dtype detection (int64 vs canonicalized int32) ----------
__global__ void detect_k(const void* ei) {
    if (threadIdx.x == 0 && blockIdx.x == 0) {
        const unsigned long long* p = (const unsigned long long*)ei;
        int ok64 = 1;
        for (int k = 0; k < 64; ++k) {
            if (p[k] >= (unsigned long long)NN) { ok64 = 0; break; }
        }
        g_is64 = ok64;
    }
}

// ---------------- Graph preprocessing ----------------
__global__ void prep_zero() {
    int i = blockIdx.x * blockDim.x + threadIdx.x;
    if (i < NN) g_cnt[i] = 0;
}

__global__ void prep_scatter(const void* __restrict__ ei,
                             const float* __restrict__ W)
{
    int e = blockIdx.x * blockDim.x + threadIdx.x;
    if (e >= EE) return;
    int s, d;
    if (g_is64) {
        const long long* p = (const long long*)ei;
        s = (int)p[e]; d = (int)p[(size_t)EE + e];
    } else {
        const int* p = (const int*)ei;
        s = p[e]; d = p[EE + e];
    }
    if ((unsigned)s >= NN || (unsigned)d >= NN) return;
    int slot = atomicAdd(&g_cnt[d], 1);
    if (slot < MAXDEG) {
        size_t p = (size_t)slot * NN + d;
        g_key[p] = ((unsigned)e << 8) | (unsigned)slot;
        Edge ed; ed.src = s; ed.w = W[e];
        g_tmp[p] = ed;
    }
}

// Per-neuron sort of packed (eid<<8|slot) keys -> edge-id order == XLA
// ScatterExpander's sequential accumulation order. 768B local per thread.
__global__ void __launch_bounds__(128) prep_sort(const float* __restrict__ act0)
{
    int i = blockIdx.x * blockDim.x + threadIdx.x;
    if (i >= NN) return;
    int d = g_cnt[i]; if (d > MAXDEG) d = MAXDEG;
    g_deg[i] = d;
    unsigned keys[MAXDEG];
    for (int s = 0; s < d; ++s)
        keys[s] = g_key[(size_t)s * NN + i];
    for (int a = 1; a < d; ++a) {               // insertion sort (eids distinct)
        unsigned k = keys[a];
        int b = a - 1;
        while (b >= 0 && keys[b] > k) { keys[b + 1] = keys[b]; --b; }
        keys[b + 1] = k;
    }
    for (int s = 0; s < d; ++s)
        g_ell[(size_t)s * NN + i] = g_tmp[(size_t)(keys[s] & 0xFFu) * NN + i];
    g_actA[i] = act0[i];
}

// ---------------- Fused simulation step ----------------
__global__ void __launch_bounds__(256) step_k(
    int t, int parity,
    unsigned kn0, unsigned kn1, unsigned kf0, unsigned kf1,
    float* __restrict__ out)
{
    int i = blockIdx.x * blockDim.x + threadIdx.x;
    if (i >= NN) return;
    const float* actIn  = parity ? g_actB : g_actA;
    float*       actOut = parity ? g_actA : g_actB;

    // agg[i]: sequential f32 chain in increasing edge id
    float acc = 0.0f;
    int d = g_deg[i];
    for (int s = 0; s < d; ++s) {
        Edge ed = g_ell[(size_t)s * NN + i];
        acc = __fadd_rn(acc, __fmul_rn(ed.w, __ldg(&actIn[ed.src])));
    }

    // Partitionable threefry: bits_i = o0 ^ o1 of cipher(key, (0, i))
    unsigned b0, b1;
    tf2x32(kn0, kn1, 0u, (unsigned)i, b0, b1);
    float noise = __fmul_rn(0.3f, bits_to_normal(b0 ^ b1));
    tf2x32(kf0, kf1, 0u, (unsigned)i, b0, b1);
    float filt = (bits_to_normal(b0 ^ b1) > 1.5f) ? 1.0f : 0.0f;

    // l = R*agg + B*(1 + noise*filt), each op individually rounded
    float l = __fadd_rn(__fmul_rn(0.025f, acc),
                        __fmul_rn(0.001f, __fadd_rn(1.0f, __fmul_rn(noise, filt))));
    float spike = (l > 0.001378f) ? 1.0f : 0.0f;

    // new_act = (agg + spikes) - ((agg / tau) * dt)
    float na = __fsub_rn(__fadd_rn(acc, spike),
                         __fmul_rn(__fdiv_rn(acc, 0.01f), 1e-4f));

    out[(size_t)i * NSTEPS + t] = spike;
    actOut[i] = na;
}

// ---------------- Host ----------------
extern "C" void kernel_launch(void* const* d_in, const int* in_sizes, int n_in,
                              void* d_out, int out_size)
{
    const float* act0 = (const float*)d_in[0];
    const float* W    = (const float*)d_in[1];
    const void*  ei   = d_in[2];
    float*       out  = (float*)d_out;

    detect_k    <<<1, 32>>>(ei);
    prep_zero   <<<(NN + 255) / 256, 256>>>();
    prep_scatter<<<(EE + 255) / 256, 256>>>(ei, W);
    prep_sort   <<<(NN + 127) / 128, 128>>>(act0);

    for (int t = 0; t < NSTEPS; ++t) {
        // Partitionable chain (host-side; t is a host constant):
        // kt = TF(key42,(0,t)); kn = TF(kt,(0,0)); kf = TF(kt,(0,1)).
        unsigned kt0, kt1, n0, n1, f0, f1;
        tf2x32(0u, 42u, 0u, (unsigned)t, kt0, kt1);
        tf2x32(kt0, kt1, 0u, 0u, n0, n1);
        tf2x32(kt0, kt1, 0u, 1u, f0, f1);
        step_k<<<(NN + 255) / 256, 256>>>(t, t & 1, n0, n1, f0, f1, out);
    }
}

// round 4
// speedup vs baseline: 1.2522x; 1.2522x over previous
#include <cuda_runtime.h>
#include <stdint.h>
#include <math.h>

// HermanModel spiking network — bit-faithful replication of the JAX/XLA-CPU
// reference (partitionable Threefry, XLA ErfInv, eid-ordered scatter chain),
// with src-clustered smem-staged gather for the per-step aggregation.

#define NN      100000
#define EE      6400000
#define MAXDEG  192
#define NSTEPS  100

#define NPB     680            // neurons per block
#define TPB     704            // threads per block (>= NPB, mult of 32)
#define NB      148            // ceil(NN/NPB) = 148 = one wave
#define CAP     49152          // max staged edges per block (mean 43520, +27 sigma)
#define NBUCK   1563           // src buckets of 64 (100000/64 rounded up)

struct __align__(8) Edge { int src; float w; };

// ---- static scratch (no allocs allowed) ----
__device__ int      g_is64;
__device__ unsigned g_thr;                       // filt bit-threshold; 0xFFFFFFFF = fallback
__device__ int      g_cnt[NN];
__device__ int      g_deg[NN];
__device__ unsigned g_key[(size_t)MAXDEG * NN];  // packed (eid<<8)|slot
__device__ Edge     g_tmp[(size_t)MAXDEG * NN];
__device__ Edge     g_ell[(size_t)MAXDEG * NN];  // eid-ordered ELL (fallback + fill source)
__device__ unsigned g_lofs[NN];                  // block-local CSR offset
__device__ int      g_m[NB];                     // edges per block
__device__ unsigned g_bcnt[(size_t)NB * NBUCK];  // bucket counts -> bases -> cursors
__device__ unsigned g_gsrc[(size_t)NB * CAP];    // gather list: src
__device__ unsigned short g_gpos[(size_t)NB * CAP]; // gather list: smem position
__device__ float    g_gw[(size_t)NB * CAP];      // gather list: weight
__device__ float    g_actA[NN];
__device__ float    g_actB[NN];
__device__ float    g_spk[(size_t)NSTEPS * NN];  // [t][i], transposed at the end

// ---------------- Threefry-2x32 (JAX's 20-round cipher) ----------------
__host__ __device__ __forceinline__ unsigned rotl32(unsigned x, int r) {
    return (x << r) | (x >> (32 - r));
}
__host__ __device__ __forceinline__ void tf2x32(unsigned k0, unsigned k1,
                                                unsigned x0, unsigned x1,
                                                unsigned &o0, unsigned &o1)
{
    unsigned k2 = k0 ^ k1 ^ 0x1BD11BDAu;
    x0 += k0; x1 += k1;
#define TF_R(r) { x0 += x1; x1 = rotl32(x1, r); x1 ^= x0; }
#define TF_G1   TF_R(13) TF_R(15) TF_R(26) TF_R(6)
#define TF_G2   TF_R(17) TF_R(29) TF_R(16) TF_R(24)
    TF_G1  x0 += k1; x1 += k2 + 1u;
    TF_G2  x0 += k2; x1 += k0 + 2u;
    TF_G1  x0 += k0; x1 += k1 + 3u;
    TF_G2  x0 += k1; x1 += k2 + 4u;
    TF_G1  x0 += k2; x1 += k0 + 5u;
#undef TF_G1
#undef TF_G2
#undef TF_R
    o0 = x0; o1 = x1;
}

// ---------------- XLA math replication (strict f32, no FMA) ----------------
__device__ __forceinline__ float xla_log1p(float v) {
    if (fabsf(v) < 1e-4f)
        return __fmul_rn(__fadd_rn(__fmul_rn(-0.5f, v), 1.0f), v);
    return (float)log((double)__fadd_rn(v, 1.0f));
}
__device__ __forceinline__ float xla_erfinv(float x) {
    float w = -xla_log1p(-__fmul_rn(x, x));
    float p;
    if (w < 5.0f) {
        w = __fadd_rn(w, -2.5f);
        p =  2.81022636e-08f;
        p = __fadd_rn( 3.43273939e-07f, __fmul_rn(p, w));
        p = __fadd_rn(-3.5233877e-06f,  __fmul_rn(p, w));
        p = __fadd_rn(-4.39150654e-06f, __fmul_rn(p, w));
        p = __fadd_rn( 0.00021858087f,  __fmul_rn(p, w));
        p = __fadd_rn(-0.00125372503f,  __fmul_rn(p, w));
        p = __fadd_rn(-0.00417768164f,  __fmul_rn(p, w));
        p = __fadd_rn( 0.246640727f,    __fmul_rn(p, w));
        p = __fadd_rn( 1.50140941f,     __fmul_rn(p, w));
    } else {
        w = __fadd_rn(sqrtf(w), -3.0f);
        p = -0.000200214257f;
        p = __fadd_rn( 0.000100950558f, __fmul_rn(p, w));
        p = __fadd_rn( 0.00134934322f,  __fmul_rn(p, w));
        p = __fadd_rn(-0.00367342844f,  __fmul_rn(p, w));
        p = __fadd_rn( 0.00573950773f,  __fmul_rn(p, w));
        p = __fadd_rn(-0.0076224613f,   __fmul_rn(p, w));
        p = __fadd_rn( 0.00943887047f,  __fmul_rn(p, w));
        p = __fadd_rn( 1.00167406f,     __fmul_rn(p, w));
        p = __fadd_rn( 2.83297682f,     __fmul_rn(p, w));
    }
    return __fmul_rn(p, x);
}
__device__ __forceinline__ float bits_to_normal(unsigned bits) {
    const float LO = -0.99999994f;   // nextafter(-1,0)
    float f = __fadd_rn(__uint_as_float((bits >> 9) | 0x3F800000u), -1.0f);
    float u = __fadd_rn(__fmul_rn(f, 2.0f), LO);
    u = fmaxf(LO, u);
    return __fmul_rn(1.41421356f, xla_erfinv(u));
}

// ---------------- init: dtype detect + filt bit-threshold ----------------
__global__ void init_k(const void* ei) {
    if (blockIdx.x || threadIdx.x) return;
    const unsigned long long* p = (const unsigned long long*)ei;
    int ok64 = 1;
    for (int k = 0; k < 64; ++k)
        if (p[k] >= (unsigned long long)NN) { ok64 = 0; break; }
    g_is64 = ok64;

    // smallest m23 with normal(m23<<9) > 1.5f  (map is monotone in m23)
    unsigned lo = 0, hi = 1u << 23;
    while (lo < hi) {
        unsigned mid = (lo + hi) >> 1;
        if (bits_to_normal(mid << 9) > 1.5f) hi = mid; else lo = mid + 1;
    }
    unsigned thr = lo, bad = 0;
    unsigned a = (thr > 512u) ? thr - 512u : 0u;
    unsigned b = (thr + 512u < (1u << 23)) ? thr + 512u : (1u << 23);
    for (unsigned m = a; m < b; ++m) {
        bool big = bits_to_normal(m << 9) > 1.5f;
        if (big != (m >= thr)) { bad = 1; break; }
    }
    g_thr = bad ? 0xFFFFFFFFu : thr;
}

// ---------------- prep ----------------
__global__ void prep_zero() {
    size_t i = (size_t)blockIdx.x * blockDim.x + threadIdx.x;
    if (i < NN) g_cnt[i] = 0;
    if (i < (size_t)NB * NBUCK) g_bcnt[i] = 0;
}

__global__ void prep_scatter(const void* __restrict__ ei,
                             const float* __restrict__ W)
{
    int e = blockIdx.x * blockDim.x + threadIdx.x;
    if (e >= EE) return;
    int s, d;
    if (g_is64) {
        const long long* p = (const long long*)ei;
        s = (int)p[e]; d = (int)p[(size_t)EE + e];
    } else {
        const int* p = (const int*)ei;
        s = p[e]; d = p[EE + e];
    }
    if ((unsigned)s >= NN || (unsigned)d >= NN) return;
    int slot = atomicAdd(&g_cnt[d], 1);
    if (slot < MAXDEG) {
        size_t p = (size_t)slot * NN + d;
        g_key[p] = ((unsigned)e << 8) | (unsigned)slot;
        Edge ed; ed.src = s; ed.w = W[e];
        g_tmp[p] = ed;
    }
}

// eid-order per neuron (XLA ScatterExpander order) + bucket counting.
__global__ void __launch_bounds__(128) prep_sort(const float* __restrict__ act0)
{
    int i = blockIdx.x * blockDim.x + threadIdx.x;
    if (i >= NN) return;
    int d = g_cnt[i]; if (d > MAXDEG) d = MAXDEG;
    g_deg[i] = d;
    unsigned keys[MAXDEG];
    for (int s = 0; s < d; ++s)
        keys[s] = g_key[(size_t)s * NN + i];
    for (int a = 1; a < d; ++a) {
        unsigned k = keys[a];
        int b = a - 1;
        while (b >= 0 && keys[b] > k) { keys[b + 1] = keys[b]; --b; }
        keys[b + 1] = k;
    }
    int blk = i / NPB;
    unsigned* bc = &g_bcnt[(size_t)blk * NBUCK];
    for (int s = 0; s < d; ++s) {
        Edge ed = g_tmp[(size_t)(keys[s] & 0xFFu) * NN + i];
        g_ell[(size_t)s * NN + i] = ed;
        atomicAdd(&bc[(unsigned)ed.src >> 6], 1u);
    }
    g_actA[i] = act0[i];
}

// per-block exclusive scan of degrees -> block-local CSR offsets
__global__ void __launch_bounds__(TPB) prep_csr()
{
    __shared__ unsigned sa[TPB], sb[TPB];
    int blk = blockIdx.x, tid = threadIdx.x;
    int i = blk * NPB + tid;
    unsigned d = (tid < NPB && i < NN) ? (unsigned)g_deg[i] : 0u;
    sa[tid] = d;
    __syncthreads();
    unsigned *in = sa, *out = sb;
    for (int off = 1; off < TPB; off <<= 1) {
        out[tid] = in[tid] + ((tid >= off) ? in[tid - off] : 0u);
        __syncthreads();
        unsigned* t = in; in = out; out = t;
    }
    unsigned incl = in[tid];
    if (tid < NPB && i < NN) g_lofs[i] = incl - d;
    if (tid == TPB - 1) g_m[blk] = (int)incl;
}

// per-block exclusive scan of bucket counts -> bases (reused as cursors)
__global__ void __launch_bounds__(256) prep_bscan()
{
    __shared__ unsigned part[256], pa[256], pb[256];
    int blk = blockIdx.x, tid = threadIdx.x;
    unsigned* c = &g_bcnt[(size_t)blk * NBUCK];
    const int PER = (NBUCK + 255) / 256;   // 7
    unsigned s = 0;
    for (int k = 0; k < PER; ++k) {
        int idx = tid * PER + k;
        if (idx < NBUCK) s += c[idx];
    }
    part[tid] = s; pa[tid] = s;
    __syncthreads();
    unsigned *in = pa, *out = pb;
    for (int off = 1; off < 256; off <<= 1) {
        out[tid] = in[tid] + ((tid >= off) ? in[tid - off] : 0u);
        __syncthreads();
        unsigned* t = in; in = out; out = t;
    }
    unsigned base = in[tid] - part[tid];
    for (int k = 0; k < PER; ++k) {
        int idx = tid * PER + k;
        if (idx < NBUCK) { unsigned v = c[idx]; c[idx] = base; base += v; }
    }
}

// place edges into src-bucket-clustered gather lists
__global__ void __launch_bounds__(128) prep_fill()
{
    int i = blockIdx.x * blockDim.x + threadIdx.x;
    if (i >= NN) return;
    int d = g_deg[i];
    int blk = i / NPB;
    unsigned lo = g_lofs[i];
    unsigned* cur = &g_bcnt[(size_t)blk * NBUCK];
    size_t base = (size_t)blk * CAP;
    for (int s = 0; s < d; ++s) {
        Edge ed = g_ell[(size_t)s * NN + i];
        unsigned idx = atomicAdd(&cur[(unsigned)ed.src >> 6], 1u);
        if (idx < CAP) {
            g_gsrc[base + idx] = (unsigned)ed.src;
            g_gpos[base + idx] = (unsigned short)(lo + (unsigned)s);
            g_gw[base + idx]   = ed.w;
        }
    }
}

// ---------------- fused simulation step ----------------
__global__ void __launch_bounds__(TPB) step_k(
    int t, int parity,
    unsigned kn0, unsigned kn1, unsigned kf0, unsigned kf1)
{
    extern __shared__ float sval[];
    int blk = blockIdx.x;
    const float* actIn  = parity ? g_actB : g_actA;
    float*       actOut = parity ? g_actA : g_actB;
    int m = g_m[blk];
    bool staged = (m <= CAP);

    if (staged) {
        size_t base = (size_t)blk * CAP;
        for (int j = threadIdx.x; j < m; j += TPB) {
            unsigned s = g_gsrc[base + j];
            unsigned short p = g_gpos[base + j];
            sval[p] = __fmul_rn(g_gw[base + j], __ldg(&actIn[s]));
        }
    }
    __syncthreads();

    int li = threadIdx.x;
    int i = blk * NPB + li;
    if (li < NPB && i < NN) {
        float acc = 0.0f;
        int d = g_deg[i];
        if (staged) {
            unsigned lo = g_lofs[i];
            for (int s = 0; s < d; ++s)
                acc = __fadd_rn(acc, sval[lo + s]);          // eid-ordered chain
        } else {
            for (int s = 0; s < d; ++s) {
                Edge ed = g_ell[(size_t)s * NN + i];
                acc = __fadd_rn(acc, __fmul_rn(ed.w, __ldg(&actIn[ed.src])));
            }
        }

        unsigned b0, b1;
        tf2x32(kf0, kf1, 0u, (unsigned)i, b0, b1);
        unsigned fb = b0 ^ b1;
        unsigned thr = g_thr;
        bool filt = (thr != 0xFFFFFFFFu) ? ((fb >> 9) >= thr)
                                         : (bits_to_normal(fb) > 1.5f);
        float l;
        if (filt) {
            tf2x32(kn0, kn1, 0u, (unsigned)i, b0, b1);
            float noise = __fmul_rn(0.3f, bits_to_normal(b0 ^ b1));
            l = __fadd_rn(__fmul_rn(0.025f, acc),
                          __fmul_rn(0.001f, __fadd_rn(1.0f, noise)));
        } else {
            l = __fadd_rn(__fmul_rn(0.025f, acc), 0.001f);   // B*(1+0) exact
        }
        float spike = (l > 0.001378f) ? 1.0f : 0.0f;
        float na = __fsub_rn(__fadd_rn(acc, spike),
                             __fmul_rn(__fdiv_rn(acc, 0.01f), 1e-4f));
        g_spk[(size_t)t * NN + i] = spike;
        actOut[i] = na;
    }
}

// ---------------- [t][i] -> [i][t] transpose ----------------
__global__ void trans_k(float* __restrict__ out)
{
    __shared__ float tile[32][33];
    int i0 = blockIdx.x * 32, t0 = blockIdx.y * 32;
    int tr = t0 + threadIdx.y, ic = i0 + threadIdx.x;
    tile[threadIdx.y][threadIdx.x] =
        (tr < NSTEPS && ic < NN) ? g_spk[(size_t)tr * NN + ic] : 0.0f;
    __syncthreads();
    int iw = i0 + threadIdx.y, tw = t0 + threadIdx.x;
    if (iw < NN && tw < NSTEPS)
        out[(size_t)iw * NSTEPS + tw] = tile[threadIdx.x][threadIdx.y];
}

// ---------------- host ----------------
extern "C" void kernel_launch(void* const* d_in, const int* in_sizes, int n_in,
                              void* d_out, int out_size)
{
    const float* act0 = (const float*)d_in[0];
    const float* W    = (const float*)d_in[1];
    const void*  ei   = d_in[2];
    float*       out  = (float*)d_out;

    cudaFuncSetAttribute(step_k, cudaFuncAttributeMaxDynamicSharedMemorySize,
                         CAP * (int)sizeof(float));

    init_k      <<<1, 32>>>(ei);
    {
        size_t zn = (size_t)NB * NBUCK;  // > NN
        prep_zero<<<(int)((zn + 255) / 256), 256>>>();
    }
    prep_scatter<<<(EE + 255) / 256, 256>>>(ei, W);
    prep_sort   <<<(NN + 127) / 128, 128>>>(act0);
    prep_csr    <<<NB, TPB>>>();
    prep_bscan  <<<NB, 256>>>();
    prep_fill   <<<(NN + 127) / 128, 128>>>();

    for (int t = 0; t < NSTEPS; ++t) {
        unsigned kt0, kt1, n0, n1, f0, f1;
        tf2x32(0u, 42u, 0u, (unsigned)t, kt0, kt1);
        tf2x32(kt0, kt1, 0u, 0u, n0, n1);
        tf2x32(kt0, kt1, 0u, 1u, f0, f1);
        step_k<<<NB, TPB, CAP * sizeof(float)>>>(t, t & 1, n0, n1, f0, f1);
    }
    trans_k<<<dim3((NN + 31) / 32, (NSTEPS + 31) / 32), dim3(32, 32)>>>(out);
}

// round 5
// speedup vs baseline: 1.2981x; 1.0367x over previous
#include <cuda_runtime.h>
#include <stdint.h>
#include <math.h>

// HermanModel spiking network — bit-faithful replication of the JAX/XLA-CPU
// reference (partitionable Threefry, XLA ErfInv, eid-ordered scatter chain).
// Step kernel: src-clustered gather with 8B/edge packed stream, 2 blocks/SM.

#define NN      100000
#define EE      6400000
#define MAXDEG  192
#define NSTEPS  100

#define NPB     340            // neurons per block
#define TPB     352            // threads per block
#define NB      295            // ceil(NN/NPB)
#define CAP     24576          // staged edges per block (mean 21760, +19 sigma); < 2^15
#define NBUCK   1563           // src buckets of 64

struct __align__(8) Edge  { int src; float w; };
struct __align__(8) GEnt  { unsigned packed; float w; };   // (src<<15)|pos, weight

// ---- static scratch (no allocs allowed) ----
__device__ int      g_is64;
__device__ unsigned g_thr;                        // filt bit-threshold; ~0u = fallback
__device__ int      g_cnt[NN];
__device__ int      g_deg[NN];
__device__ unsigned g_key[(size_t)MAXDEG * NN];   // packed (eid<<8)|slot
__device__ Edge     g_tmp[(size_t)MAXDEG * NN];
__device__ Edge     g_ell[(size_t)MAXDEG * NN];   // eid-ordered ELL (fallback + fill src)
__device__ unsigned g_lofs[NN];                   // block-local CSR offset
__device__ int      g_m[NB];                      // edges per block
__device__ unsigned g_bcnt[(size_t)NB * NBUCK];   // bucket counts -> bases -> cursors
__device__ GEnt     g_g[(size_t)NB * CAP];        // src-clustered gather list
__device__ float    g_actA[NN];
__device__ float    g_actB[NN];
__device__ float    g_spk[(size_t)NSTEPS * NN];   // [t][i]

// ---------------- Threefry-2x32 (JAX's 20-round cipher) ----------------
__host__ __device__ __forceinline__ unsigned rotl32(unsigned x, int r) {
    return (x << r) | (x >> (32 - r));
}
__host__ __device__ __forceinline__ void tf2x32(unsigned k0, unsigned k1,
                                                unsigned x0, unsigned x1,
                                                unsigned &o0, unsigned &o1)
{
    unsigned k2 = k0 ^ k1 ^ 0x1BD11BDAu;
    x0 += k0; x1 += k1;
#define TF_R(r) { x0 += x1; x1 = rotl32(x1, r); x1 ^= x0; }
#define TF_G1   TF_R(13) TF_R(15) TF_R(26) TF_R(6)
#define TF_G2   TF_R(17) TF_R(29) TF_R(16) TF_R(24)
    TF_G1  x0 += k1; x1 += k2 + 1u;
    TF_G2  x0 += k2; x1 += k0 + 2u;
    TF_G1  x0 += k0; x1 += k1 + 3u;
    TF_G2  x0 += k1; x1 += k2 + 4u;
    TF_G1  x0 += k2; x1 += k0 + 5u;
#undef TF_G1
#undef TF_G2
#undef TF_R
    o0 = x0; o1 = x1;
}

// ---------------- XLA math replication (strict f32, no FMA) ----------------
__device__ __forceinline__ float xla_log1p(float v) {
    if (fabsf(v) < 1e-4f)
        return __fmul_rn(__fadd_rn(__fmul_rn(-0.5f, v), 1.0f), v);
    return (float)log((double)__fadd_rn(v, 1.0f));
}
__device__ __forceinline__ float xla_erfinv(float x) {
    float w = -xla_log1p(-__fmul_rn(x, x));
    float p;
    if (w < 5.0f) {
        w = __fadd_rn(w, -2.5f);
        p =  2.81022636e-08f;
        p = __fadd_rn( 3.43273939e-07f, __fmul_rn(p, w));
        p = __fadd_rn(-3.5233877e-06f,  __fmul_rn(p, w));
        p = __fadd_rn(-4.39150654e-06f, __fmul_rn(p, w));
        p = __fadd_rn( 0.00021858087f,  __fmul_rn(p, w));
        p = __fadd_rn(-0.00125372503f,  __fmul_rn(p, w));
        p = __fadd_rn(-0.00417768164f,  __fmul_rn(p, w));
        p = __fadd_rn( 0.246640727f,    __fmul_rn(p, w));
        p = __fadd_rn( 1.50140941f,     __fmul_rn(p, w));
    } else {
        w = __fadd_rn(sqrtf(w), -3.0f);
        p = -0.000200214257f;
        p = __fadd_rn( 0.000100950558f, __fmul_rn(p, w));
        p = __fadd_rn( 0.00134934322f,  __fmul_rn(p, w));
        p = __fadd_rn(-0.00367342844f,  __fmul_rn(p, w));
        p = __fadd_rn( 0.00573950773f,  __fmul_rn(p, w));
        p = __fadd_rn(-0.0076224613f,   __fmul_rn(p, w));
        p = __fadd_rn( 0.00943887047f,  __fmul_rn(p, w));
        p = __fadd_rn( 1.00167406f,     __fmul_rn(p, w));
        p = __fadd_rn( 2.83297682f,     __fmul_rn(p, w));
    }
    return __fmul_rn(p, x);
}
__device__ __forceinline__ float bits_to_normal(unsigned bits) {
    const float LO = -0.99999994f;
    float f = __fadd_rn(__uint_as_float((bits >> 9) | 0x3F800000u), -1.0f);
    float u = __fadd_rn(__fmul_rn(f, 2.0f), LO);
    u = fmaxf(LO, u);
    return __fmul_rn(1.41421356f, xla_erfinv(u));
}

// ---------------- init: dtype detect + filt bit-threshold ----------------
__global__ void init_k(const void* ei) {
    if (blockIdx.x || threadIdx.x) return;
    const unsigned long long* p = (const unsigned long long*)ei;
    int ok64 = 1;
    for (int k = 0; k < 64; ++k)
        if (p[k] >= (unsigned long long)NN) { ok64 = 0; break; }
    g_is64 = ok64;

    unsigned lo = 0, hi = 1u << 23;
    while (lo < hi) {
        unsigned mid = (lo + hi) >> 1;
        if (bits_to_normal(mid << 9) > 1.5f) hi = mid; else lo = mid + 1;
    }
    unsigned thr = lo, bad = 0;
    unsigned a = (thr > 512u) ? thr - 512u : 0u;
    unsigned b = (thr + 512u < (1u << 23)) ? thr + 512u : (1u << 23);
    for (unsigned m = a; m < b; ++m) {
        bool big = bits_to_normal(m << 9) > 1.5f;
        if (big != (m >= thr)) { bad = 1; break; }
    }
    g_thr = bad ? 0xFFFFFFFFu : thr;
}

// ---------------- prep ----------------
__global__ void prep_zero() {
    size_t i = (size_t)blockIdx.x * blockDim.x + threadIdx.x;
    if (i < NN) g_cnt[i] = 0;
    if (i < (size_t)NB * NBUCK) g_bcnt[i] = 0;
}

__global__ void prep_scatter(const void* __restrict__ ei,
                             const float* __restrict__ W)
{
    int e = blockIdx.x * blockDim.x + threadIdx.x;
    if (e >= EE) return;
    int s, d;
    if (g_is64) {
        const long long* p = (const long long*)ei;
        s = (int)p[e]; d = (int)p[(size_t)EE + e];
    } else {
        const int* p = (const int*)ei;
        s = p[e]; d = p[EE + e];
    }
    if ((unsigned)s >= NN || (unsigned)d >= NN) return;
    int slot = atomicAdd(&g_cnt[d], 1);
    if (slot < MAXDEG) {
        size_t p = (size_t)slot * NN + d;
        g_key[p] = ((unsigned)e << 8) | (unsigned)slot;
        Edge ed; ed.src = s; ed.w = W[e];
        g_tmp[p] = ed;
    }
}

// eid-order per neuron (XLA ScatterExpander order) + bucket counting.
__global__ void __launch_bounds__(128) prep_sort(const float* __restrict__ act0)
{
    int i = blockIdx.x * blockDim.x + threadIdx.x;
    if (i >= NN) return;
    int d = g_cnt[i]; if (d > MAXDEG) d = MAXDEG;
    g_deg[i] = d;
    unsigned keys[MAXDEG];
    for (int s = 0; s < d; ++s)
        keys[s] = g_key[(size_t)s * NN + i];
    for (int a = 1; a < d; ++a) {
        unsigned k = keys[a];
        int b = a - 1;
        while (b >= 0 && keys[b] > k) { keys[b + 1] = keys[b]; --b; }
        keys[b + 1] = k;
    }
    int blk = i / NPB;
    unsigned* bc = &g_bcnt[(size_t)blk * NBUCK];
    for (int s = 0; s < d; ++s) {
        Edge ed = g_tmp[(size_t)(keys[s] & 0xFFu) * NN + i];
        g_ell[(size_t)s * NN + i] = ed;
        atomicAdd(&bc[(unsigned)ed.src >> 6], 1u);
    }
    g_actA[i] = act0[i];
}

// per-block exclusive scan of degrees -> block-local CSR offsets
__global__ void __launch_bounds__(TPB) prep_csr()
{
    __shared__ unsigned sa[TPB], sb[TPB];
    int blk = blockIdx.x, tid = threadIdx.x;
    int i = blk * NPB + tid;
    unsigned d = (tid < NPB && i < NN) ? (unsigned)g_deg[i] : 0u;
    sa[tid] = d;
    __syncthreads();
    unsigned *in = sa, *out = sb;
    for (int off = 1; off < TPB; off <<= 1) {
        out[tid] = in[tid] + ((tid >= off) ? in[tid - off] : 0u);
        __syncthreads();
        unsigned* t = in; in = out; out = t;
    }
    unsigned incl = in[tid];
    if (tid < NPB && i < NN) g_lofs[i] = incl - d;
    if (tid == TPB - 1) g_m[blk] = (int)incl;
}

// per-block exclusive scan of bucket counts -> bases (reused as cursors)
__global__ void __launch_bounds__(256) prep_bscan()
{
    __shared__ unsigned part[256], pa[256], pb[256];
    int blk = blockIdx.x, tid = threadIdx.x;
    unsigned* c = &g_bcnt[(size_t)blk * NBUCK];
    const int PER = (NBUCK + 255) / 256;   // 7
    unsigned s = 0;
    for (int k = 0; k < PER; ++k) {
        int idx = tid * PER + k;
        if (idx < NBUCK) s += c[idx];
    }
    part[tid] = s; pa[tid] = s;
    __syncthreads();
    unsigned *in = pa, *out = pb;
    for (int off = 1; off < 256; off <<= 1) {
        out[tid] = in[tid] + ((tid >= off) ? in[tid - off] : 0u);
        __syncthreads();
        unsigned* t = in; in = out; out = t;
    }
    unsigned base = in[tid] - part[tid];
    for (int k = 0; k < PER; ++k) {
        int idx = tid * PER + k;
        if (idx < NBUCK) { unsigned v = c[idx]; c[idx] = base; base += v; }
    }
}

// place edges into src-bucket-clustered gather lists (packed 8B entries)
__global__ void __launch_bounds__(128) prep_fill()
{
    int i = blockIdx.x * blockDim.x + threadIdx.x;
    if (i >= NN) return;
    int d = g_deg[i];
    int blk = i / NPB;
    unsigned lo = g_lofs[i];
    unsigned* cur = &g_bcnt[(size_t)blk * NBUCK];
    size_t base = (size_t)blk * CAP;
    for (int s = 0; s < d; ++s) {
        Edge ed = g_ell[(size_t)s * NN + i];
        unsigned idx = atomicAdd(&cur[(unsigned)ed.src >> 6], 1u);
        unsigned pos = lo + (unsigned)s;
        if (idx < CAP && pos < CAP) {
            GEnt g; g.packed = ((unsigned)ed.src << 15) | pos; g.w = ed.w;
            g_g[base + idx] = g;
        }
    }
}

// ---------------- fused simulation step ----------------
__global__ void __launch_bounds__(TPB) step_k(
    int t, int parity,
    unsigned kn0, unsigned kn1, unsigned kf0, unsigned kf1)
{
    extern __shared__ float sval[];          // CAP floats = 96KB
    int blk = blockIdx.x;
    const float* actIn  = parity ? g_actB : g_actA;
    float*       actOut = parity ? g_actA : g_actB;
    int m = g_m[blk];
    bool staged = (m <= CAP);

    if (staged) {
        const GEnt* gl = &g_g[(size_t)blk * CAP];
        for (int j = threadIdx.x; j < m; j += TPB) {
            GEnt g = gl[j];
            sval[g.packed & 0x7FFFu] =
                __fmul_rn(g.w, __ldg(&actIn[g.packed >> 15]));
        }
    }
    __syncthreads();

    int li = threadIdx.x;
    int i = blk * NPB + li;
    if (li < NPB && i < NN) {
        float acc = 0.0f;
        int d = g_deg[i];
        if (staged) {
            unsigned lo = g_lofs[i];
            for (int s = 0; s < d; ++s)
                acc = __fadd_rn(acc, sval[lo + s]);          // eid-ordered chain
        } else {
            for (int s = 0; s < d; ++s) {
                Edge ed = g_ell[(size_t)s * NN + i];
                acc = __fadd_rn(acc, __fmul_rn(ed.w, __ldg(&actIn[ed.src])));
            }
        }

        unsigned b0, b1;
        tf2x32(kf0, kf1, 0u, (unsigned)i, b0, b1);
        unsigned fb = b0 ^ b1;
        unsigned thr = g_thr;
        bool filt = (thr != 0xFFFFFFFFu) ? ((fb >> 9) >= thr)
                                         : (bits_to_normal(fb) > 1.5f);
        float l;
        if (filt) {
            tf2x32(kn0, kn1, 0u, (unsigned)i, b0, b1);
            float noise = __fmul_rn(0.3f, bits_to_normal(b0 ^ b1));
            l = __fadd_rn(__fmul_rn(0.025f, acc),
                          __fmul_rn(0.001f, __fadd_rn(1.0f, noise)));
        } else {
            l = __fadd_rn(__fmul_rn(0.025f, acc), 0.001f);
        }
        float spike = (l > 0.001378f) ? 1.0f : 0.0f;
        float na = __fsub_rn(__fadd_rn(acc, spike),
                             __fmul_rn(__fdiv_rn(acc, 0.01f), 1e-4f));
        g_spk[(size_t)t * NN + i] = spike;
        actOut[i] = na;
    }
}

// ---------------- [t][i] -> [i][t] transpose ----------------
__global__ void trans_k(float* __restrict__ out)
{
    __shared__ float tile[32][33];
    int i0 = blockIdx.x * 32, t0 = blockIdx.y * 32;
    int tr = t0 + threadIdx.y, ic = i0 + threadIdx.x;
    tile[threadIdx.y][threadIdx.x] =
        (tr < NSTEPS && ic < NN) ? g_spk[(size_t)tr * NN + ic] : 0.0f;
    __syncthreads();
    int iw = i0 + threadIdx.y, tw = t0 + threadIdx.x;
    if (iw < NN && tw < NSTEPS)
        out[(size_t)iw * NSTEPS + tw] = tile[threadIdx.x][threadIdx.y];
}

// ---------------- host ----------------
extern "C" void kernel_launch(void* const* d_in, const int* in_sizes, int n_in,
                              void* d_out, int out_size)
{
    const float* act0 = (const float*)d_in[0];
    const float* W    = (const float*)d_in[1];
    const void*  ei   = d_in[2];
    float*       out  = (float*)d_out;

    cudaFuncSetAttribute(step_k, cudaFuncAttributeMaxDynamicSharedMemorySize,
                         CAP * (int)sizeof(float));

    init_k      <<<1, 32>>>(ei);
    {
        size_t zn = (size_t)NB * NBUCK;
        prep_zero<<<(int)((zn + 255) / 256), 256>>>();
    }
    prep_scatter<<<(EE + 255) / 256, 256>>>(ei, W);
    prep_sort   <<<(NN + 127) / 128, 128>>>(act0);
    prep_csr    <<<NB, TPB>>>();
    prep_bscan  <<<NB, 256>>>();
    prep_fill   <<<(NN + 127) / 128, 128>>>();

    for (int t = 0; t < NSTEPS; ++t) {
        unsigned kt0, kt1, n0, n1, f0, f1;
        tf2x32(0u, 42u, 0u, (unsigned)t, kt0, kt1);
        tf2x32(kt0, kt1, 0u, 0u, n0, n1);
        tf2x32(kt0, kt1, 0u, 1u, f0, f1);
        step_k<<<NB, TPB, CAP * sizeof(float)>>>(t, t & 1, n0, n1, f0, f1);
    }
    trans_k<<<dim3((NN + 31) / 32, (NSTEPS + 31) / 32), dim3(32, 32)>>>(out);
}